// round 16
// baseline (speedup 1.0000x reference)
#include <cuda_runtime.h>
#include <cuda_fp16.h>
#include <math.h>

#define BB 512
#define TT 512

// ---------------- device scratch (allocation-free rule) ----------------
__device__ __half g_gxh[(size_t)TT * BB * 512];   // gate pre-activations (fp16)
__device__ float  g_h1[(size_t)BB * TT * 32];     // layer1 output
__device__ float  g_h2[(size_t)BB * TT * 48];     // layer2 output

__device__ __forceinline__ float sig_(float x) { return 1.0f / (1.0f + __expf(-x)); }
__device__ __forceinline__ float th_(float x) { return 1.0f - 2.0f / (__expf(2.0f * x) + 1.0f); }

// ---------------- mma helpers (verified R8/R13/R15) ----------------
__device__ __forceinline__ unsigned smem_u32(const void* p) {
    return (unsigned)__cvta_generic_to_shared(p);
}
__device__ __forceinline__ void ldmx4(unsigned& a0, unsigned& a1, unsigned& a2,
                                      unsigned& a3, unsigned addr) {
    asm volatile("ldmatrix.sync.aligned.m8n8.x4.shared.b16 {%0,%1,%2,%3}, [%4];"
                 : "=r"(a0), "=r"(a1), "=r"(a2), "=r"(a3) : "r"(addr));
}
__device__ __forceinline__ void mma16816(float* d, unsigned a0, unsigned a1,
                                         unsigned a2, unsigned a3,
                                         unsigned b0, unsigned b1) {
    asm volatile(
        "mma.sync.aligned.m16n8k16.row.col.f32.f16.f16.f32 "
        "{%0,%1,%2,%3}, {%4,%5,%6,%7}, {%8,%9}, {%0,%1,%2,%3};"
        : "+f"(d[0]), "+f"(d[1]), "+f"(d[2]), "+f"(d[3])
        : "r"(a0), "r"(a1), "r"(a2), "r"(a3), "r"(b0), "r"(b1));
}

// ---------------------------------------------------------------------------
// Input projection via tensor cores, coalesced stores (R13-proven WIN).
// ---------------------------------------------------------------------------
template <int D, int N>
__global__ void __launch_bounds__(256)
lstm_projM(const float* __restrict__ xin, const float* __restrict__ Wih,
           const float* __restrict__ bih, const float* __restrict__ bhh,
           __half* __restrict__ gx)
{
    constexpr int KT = D / 16;
    constexpr int NTILES = N / 64;
    constexpr int NCW = N / 8;
    constexpr int XPAD = D + 8;
    constexpr int OPAD = N + 8;

    __shared__ __align__(16) __half xs[32][XPAD];
    __shared__ __align__(16) __half os[32][OPAD];

    const int tid = threadIdx.x;
    const int w = tid >> 5, l = tid & 31;
    const int l4 = l & 3, lq = l >> 2;
    const int wbase = w * NCW;

    unsigned bf[KT][NTILES][2];
#pragma unroll
    for (int kt = 0; kt < KT; kt++)
#pragma unroll
        for (int ti = 0; ti < NTILES; ti++) {
            int n = wbase + ti * 8 + lq;
            int k0 = kt * 16 + 2 * l4;
            __half2 v0 = __floats2half2_rn(__ldg(&Wih[n * D + k0]),
                                           __ldg(&Wih[n * D + k0 + 1]));
            __half2 v1 = __floats2half2_rn(__ldg(&Wih[n * D + k0 + 8]),
                                           __ldg(&Wih[n * D + k0 + 9]));
            bf[kt][ti][0] = *(unsigned*)&v0;
            bf[kt][ti][1] = *(unsigned*)&v1;
        }
    float2 b2[NTILES];
#pragma unroll
    for (int ti = 0; ti < NTILES; ti++) {
        int n0 = wbase + ti * 8 + 2 * l4;
        b2[ti] = make_float2(__ldg(&bih[n0]) + __ldg(&bhh[n0]),
                             __ldg(&bih[n0 + 1]) + __ldg(&bhh[n0 + 1]));
    }

    const int arow = l & 15, acg = (l >> 4) * 8;
    const int ntiles_tot = (BB * TT) / 32;

#pragma unroll 1
    for (int tile = blockIdx.x; tile < ntiles_tot; tile += gridDim.x) {
        __syncthreads();
#pragma unroll 1
        for (int i = tid; i < 32 * (D / 4); i += 256) {
            int row = i / (D / 4), k4 = i % (D / 4);
            float4 v = ((const float4*)(xin + (size_t)(tile * 32 + row) * D))[k4];
            *(__half2*)&xs[row][4 * k4]     = __floats2half2_rn(v.x, v.y);
            *(__half2*)&xs[row][4 * k4 + 2] = __floats2half2_rn(v.z, v.w);
        }
        __syncthreads();

#pragma unroll
        for (int mt = 0; mt < 2; mt++) {
            unsigned aa[KT][4];
#pragma unroll
            for (int kt = 0; kt < KT; kt++)
                ldmx4(aa[kt][0], aa[kt][1], aa[kt][2], aa[kt][3],
                      smem_u32(&xs[mt * 16 + arow][acg + 16 * kt]));

            float d[NTILES][4];
#pragma unroll
            for (int ti = 0; ti < NTILES; ti++) {
                d[ti][0] = b2[ti].x; d[ti][1] = b2[ti].y;
                d[ti][2] = b2[ti].x; d[ti][3] = b2[ti].y;
            }
#pragma unroll
            for (int kt = 0; kt < KT; kt++)
#pragma unroll
                for (int ti = 0; ti < NTILES; ti++)
                    mma16816(d[ti], aa[kt][0], aa[kt][1], aa[kt][2], aa[kt][3],
                             bf[kt][ti][0], bf[kt][ti][1]);

#pragma unroll
            for (int ti = 0; ti < NTILES; ti++)
#pragma unroll
                for (int rr = 0; rr < 2; rr++)
                    *(__half2*)&os[mt * 16 + lq + 8 * rr][wbase + ti * 8 + 2 * l4] =
                        __floats2half2_rn(d[ti][2 * rr], d[ti][2 * rr + 1]);
        }
        __syncthreads();

#pragma unroll 1
        for (int i = tid; i < 32 * (N / 8); i += 256) {
            int row = i / (N / 8), c8 = i % (N / 8);
            int m = tile * 32 + row;
            int b = m >> 9, t = m & 511;
            *(float4*)(gx + ((size_t)t * BB + b) * N + 8 * c8) =
                *(const float4*)&os[row][8 * c8];
        }
    }
}

// ---------------------------------------------------------------------------
// Small-layer recurrence via single-CTA tensor-core mma (NEW).
// CTA owns 16 batch rows and ALL H h-cols. Warp j owns h-cols [8j,8j+8) ->
// n-tiles {i,f,g,o} at gate cols H*g+8j (R15-verified layout). Whh in
// register B-fragments; h double-buffered fp16 in smem; in-register
// epilogue; ONE __syncthreads per step. Grid = 32 (latency-bound).
// ---------------------------------------------------------------------------
template <int H>
__global__ void __launch_bounds__(4 * H)
lstm_recur_smallM(const __half* __restrict__ gx,  // [T][B][4H] fp16
                  const float* __restrict__ Whh,  // [4H][H]
                  float* __restrict__ out)        // [B][T][H] fp32
{
    constexpr int G = 4 * H;
    constexpr int KT = H / 16;
    constexpr int HPAD = H + 8;

    __shared__ __align__(16) __half hsm[2][16][HPAD];

    const int tid = threadIdx.x;
    const int w = tid >> 5, l = tid & 31;
    const int l4 = l & 3, lq = l >> 2;
    const int b0 = blockIdx.x * 16;
    const int hb = 8 * w;                 // warp h-col base

    // B fragments from Whh (n = H*g + hb + lq)
    unsigned bf[KT][4][2];
#pragma unroll
    for (int kt = 0; kt < KT; kt++)
#pragma unroll
        for (int g = 0; g < 4; g++) {
            int n = H * g + hb + lq;
            int k0 = 16 * kt + 2 * l4;
            __half2 v0 = __floats2half2_rn(__ldg(&Whh[n * H + k0]),
                                           __ldg(&Whh[n * H + k0 + 1]));
            __half2 v1 = __floats2half2_rn(__ldg(&Whh[n * H + k0 + 8]),
                                           __ldg(&Whh[n * H + k0 + 9]));
            bf[kt][g][0] = *(unsigned*)&v0;
            bf[kt][g][1] = *(unsigned*)&v1;
        }

    // zero buffer 1 (read at t=0)
    for (int i = tid; i < 16 * HPAD / 2; i += 4 * H)
        ((unsigned*)&hsm[1][0][0])[i] = 0u;

    float c[4];
#pragma unroll
    for (int i = 0; i < 4; i++) c[i] = 0.f;

    const int arow = l & 15, acg = (l >> 4) * 8;

    // gx fragments: (g, rr) -> half2 at row b0+lq+8rr, col H*g + hb + 2*l4
    unsigned gxf[8];
    {
        const __half* gp = gx + (size_t)(b0 + lq) * G + hb + 2 * l4;
#pragma unroll
        for (int g = 0; g < 4; g++)
#pragma unroll
            for (int rr = 0; rr < 2; rr++)
                gxf[g * 2 + rr] = *(const unsigned*)(gp + g * H + (size_t)rr * 8 * G);
    }
    __syncthreads();

    for (int t = 0; t < TT; t++) {
        const int rb = (t + 1) & 1;
        const int wb = t & 1;

        unsigned gxn[8];
        if (t + 1 < TT) {
            const __half* gp = gx + ((size_t)(t + 1) * BB + (b0 + lq)) * G + hb + 2 * l4;
#pragma unroll
            for (int g = 0; g < 4; g++)
#pragma unroll
                for (int rr = 0; rr < 2; rr++)
                    gxn[g * 2 + rr] = *(const unsigned*)(gp + g * H + (size_t)rr * 8 * G);
        }

        float d[4][4];
#pragma unroll
        for (int g = 0; g < 4; g++)
#pragma unroll
            for (int rr = 0; rr < 2; rr++) {
                float2 f = __half22float2(*(__half2*)&gxf[g * 2 + rr]);
                d[g][2 * rr + 0] = f.x;
                d[g][2 * rr + 1] = f.y;
            }

#pragma unroll
        for (int kt = 0; kt < KT; kt++) {
            unsigned a0, a1, a2, a3;
            ldmx4(a0, a1, a2, a3, smem_u32(&hsm[rb][arow][acg + 16 * kt]));
#pragma unroll
            for (int g = 0; g < 4; g++)
                mma16816(d[g], a0, a1, a2, a3, bf[kt][g][0], bf[kt][g][1]);
        }

        float h[4];
#pragma unroll
        for (int reg = 0; reg < 4; reg++) {
            float gi = d[0][reg], gF = d[1][reg], gg = d[2][reg], go = d[3][reg];
            c[reg] = sig_(gF) * c[reg] + sig_(gi) * th_(gg);
            h[reg] = sig_(go) * th_(c[reg]);
        }
        *(__half2*)&hsm[wb][lq][hb + 2 * l4]     = __floats2half2_rn(h[0], h[1]);
        *(__half2*)&hsm[wb][lq + 8][hb + 2 * l4] = __floats2half2_rn(h[2], h[3]);

        {
            int hc = hb + 2 * l4;
            *(float2*)(out + ((size_t)(b0 + lq) * TT + t) * H + hc) = make_float2(h[0], h[1]);
            *(float2*)(out + ((size_t)(b0 + lq + 8) * TT + t) * H + hc) = make_float2(h[2], h[3]);
        }
#pragma unroll
        for (int i = 0; i < 8; i++) gxf[i] = gxn[i];
        __syncthreads();
    }
}

// ---------------------------------------------------------------------------
// Layer-3 recurrence: 4-CTA cluster, tensor-core mma (R15-proven WIN).
// ---------------------------------------------------------------------------
#define CLUSTER 4
#define HPAD3 136   // half stride per h row (272B -> conflict-free ldmatrix)

__global__ void __launch_bounds__(128, 1) __cluster_dims__(CLUSTER, 1, 1)
lstm_recur_cluster(const __half* __restrict__ gx,   // [T][B][512] fp16
                   const float* __restrict__ Whh,   // [512][128] Whh3
                   float* __restrict__ out,         // [B][T][128]
                   float* __restrict__ hn)          // [B][128]
{
    __shared__ __align__(16) __half hsm[2][16][HPAD3];

    const int tid = threadIdx.x;
    const int w = tid >> 5, l = tid & 31;
    const int l4 = l & 3, lq = l >> 2;
    unsigned rank;
    asm("mov.u32 %0, %%cluster_ctarank;" : "=r"(rank));
    const int b0 = (blockIdx.x >> 2) * 16;
    const int hbase = 32 * (int)rank + 8 * w;

    unsigned bf[8][4][2];
#pragma unroll
    for (int kt = 0; kt < 8; kt++)
#pragma unroll
        for (int g = 0; g < 4; g++) {
            int n = 128 * g + hbase + lq;
            int k0 = 16 * kt + 2 * l4;
            __half2 v0 = __floats2half2_rn(__ldg(&Whh[n * 128 + k0]),
                                           __ldg(&Whh[n * 128 + k0 + 1]));
            __half2 v1 = __floats2half2_rn(__ldg(&Whh[n * 128 + k0 + 8]),
                                           __ldg(&Whh[n * 128 + k0 + 9]));
            bf[kt][g][0] = *(unsigned*)&v0;
            bf[kt][g][1] = *(unsigned*)&v1;
        }

    for (int i = tid; i < 16 * HPAD3 / 2; i += 128)
        ((unsigned*)&hsm[1][0][0])[i] = 0u;

    unsigned mybase = smem_u32(&hsm[0][0][0]);
    unsigned peer[CLUSTER];
#pragma unroll
    for (int r = 0; r < CLUSTER; r++)
        asm("mapa.shared::cluster.u32 %0, %1, %2;" : "=r"(peer[r]) : "r"(mybase), "r"(r));

    __syncthreads();
    asm volatile("barrier.cluster.arrive.aligned;" ::: "memory");
    asm volatile("barrier.cluster.wait.aligned;" ::: "memory");

    float c[4];
#pragma unroll
    for (int i = 0; i < 4; i++) c[i] = 0.f;

    const int arow = l & 15, acg = (l >> 4) * 8;

    unsigned gxf[8];
    {
        const __half* gp = gx + (size_t)(b0 + lq) * 512 + hbase + 2 * l4;
#pragma unroll
        for (int g = 0; g < 4; g++)
#pragma unroll
            for (int rr = 0; rr < 2; rr++)
                gxf[g * 2 + rr] = *(const unsigned*)(gp + g * 128 + rr * 8 * 512);
    }

    for (int t = 0; t < TT; t++) {
        const int rb = (t + 1) & 1;
        const int wb = t & 1;

        unsigned gxn[8];
        if (t + 1 < TT) {
            const __half* gp = gx + ((size_t)(t + 1) * BB + (b0 + lq)) * 512 + hbase + 2 * l4;
#pragma unroll
            for (int g = 0; g < 4; g++)
#pragma unroll
                for (int rr = 0; rr < 2; rr++)
                    gxn[g * 2 + rr] = *(const unsigned*)(gp + g * 128 + rr * 8 * 512);
        }

        float d[4][4];
#pragma unroll
        for (int g = 0; g < 4; g++)
#pragma unroll
            for (int rr = 0; rr < 2; rr++) {
                float2 f = __half22float2(*(__half2*)&gxf[g * 2 + rr]);
                d[g][2 * rr + 0] = f.x;
                d[g][2 * rr + 1] = f.y;
            }

#pragma unroll
        for (int kt = 0; kt < 8; kt++) {
            unsigned a0, a1, a2, a3;
            ldmx4(a0, a1, a2, a3, smem_u32(&hsm[rb][arow][acg + 16 * kt]));
#pragma unroll
            for (int g = 0; g < 4; g++)
                mma16816(d[g], a0, a1, a2, a3, bf[kt][g][0], bf[kt][g][1]);
        }

        float h[4];
#pragma unroll
        for (int reg = 0; reg < 4; reg++) {
            float gi = d[0][reg], gF = d[1][reg], gg = d[2][reg], go = d[3][reg];
            c[reg] = sig_(gF) * c[reg] + sig_(gi) * th_(gg);
            h[reg] = sig_(go) * th_(c[reg]);
        }
        __half2 hA = __floats2half2_rn(h[0], h[1]);
        __half2 hB = __floats2half2_rn(h[2], h[3]);
        unsigned offA = ((wb * 16 + lq) * HPAD3 + hbase + 2 * l4) * 2;
        unsigned offB = ((wb * 16 + lq + 8) * HPAD3 + hbase + 2 * l4) * 2;
        unsigned hA32 = *(unsigned*)&hA, hB32 = *(unsigned*)&hB;
#pragma unroll
        for (int r = 0; r < CLUSTER; r++) {
            asm volatile("st.shared::cluster.u32 [%0], %1;" :: "r"(peer[r] + offA), "r"(hA32) : "memory");
            asm volatile("st.shared::cluster.u32 [%0], %1;" :: "r"(peer[r] + offB), "r"(hB32) : "memory");
        }
        asm volatile("barrier.cluster.arrive.aligned;" ::: "memory");

        {
            int hc = hbase + 2 * l4;
            *(float2*)(out + ((size_t)(b0 + lq) * TT + t) * 128 + hc) = make_float2(h[0], h[1]);
            *(float2*)(out + ((size_t)(b0 + lq + 8) * TT + t) * 128 + hc) = make_float2(h[2], h[3]);
            if (t == TT - 1) {
                *(float2*)(hn + (size_t)(b0 + lq) * 128 + hc) = make_float2(h[0], h[1]);
                *(float2*)(hn + (size_t)(b0 + lq + 8) * 128 + hc) = make_float2(h[2], h[3]);
            }
        }
#pragma unroll
        for (int i = 0; i < 8; i++) gxf[i] = gxn[i];

        asm volatile("barrier.cluster.wait.aligned;" ::: "memory");
    }
}

// ---------------------------------------------------------------------------
extern "C" void kernel_launch(void* const* d_in, const int* in_sizes, int n_in,
                              void* d_out, int out_size)
{
    const float* z    = (const float*)d_in[0];
    const float* Wih1 = (const float*)d_in[1];
    const float* Whh1 = (const float*)d_in[2];
    const float* bih1 = (const float*)d_in[3];
    const float* bhh1 = (const float*)d_in[4];
    const float* Wih2 = (const float*)d_in[5];
    const float* Whh2 = (const float*)d_in[6];
    const float* bih2 = (const float*)d_in[7];
    const float* bhh2 = (const float*)d_in[8];
    const float* Wih3 = (const float*)d_in[9];
    const float* Whh3 = (const float*)d_in[10];
    const float* bih3 = (const float*)d_in[11];
    const float* bhh3 = (const float*)d_in[12];

    float* dec = (float*)d_out;                        // [B,T,128]
    float* hn  = dec + (size_t)BB * TT * 128;          // [1,B,128]

    __half* gx;
    float *h1, *h2;
    cudaGetSymbolAddress((void**)&gx, g_gxh);
    cudaGetSymbolAddress((void**)&h1, g_h1);
    cudaGetSymbolAddress((void**)&h2, g_h2);

    // Layer 1: 64 -> 32
    lstm_projM<64, 128><<<2048, 256>>>(z, Wih1, bih1, bhh1, gx);
    lstm_recur_smallM<32><<<BB / 16, 128>>>(gx, Whh1, h1);

    // Layer 2: 32 -> 48
    lstm_projM<32, 192><<<2048, 256>>>(h1, Wih2, bih2, bhh2, gx);
    lstm_recur_smallM<48><<<BB / 16, 192>>>(gx, Whh2, h2);

    // Layer 3: 48 -> 128
    lstm_projM<48, 512><<<2048, 256>>>(h2, Wih3, bih3, bhh3, gx);
    lstm_recur_cluster<<<BB / 16 * CLUSTER, 128>>>(gx, Whh3, dec, hn);
}

// round 17
// speedup vs baseline: 2.2074x; 2.2074x over previous
#include <cuda_runtime.h>
#include <cuda_fp16.h>
#include <math.h>

#define BB 512
#define TT 512

// ---------------- device scratch (allocation-free rule) ----------------
__device__ __half g_gxh[(size_t)TT * BB * 512];   // gate pre-activations (fp16)
__device__ float  g_h1[(size_t)BB * TT * 32];     // layer1 output
__device__ float  g_h2[(size_t)BB * TT * 48];     // layer2 output

// ---------------- f32x2 helpers ----------------
__device__ __forceinline__ unsigned long long pk2(float a, float b) {
    unsigned long long r;
    asm("mov.b64 %0, {%1,%2};" : "=l"(r) : "f"(a), "f"(b));
    return r;
}
__device__ __forceinline__ void fma2_(unsigned long long& d, unsigned long long a,
                                      unsigned long long b) {
    asm("fma.rn.f32x2 %0, %1, %2, %0;" : "+l"(d) : "l"(a), "l"(b));
}
__device__ __forceinline__ unsigned long long add2_(unsigned long long a,
                                                    unsigned long long b) {
    unsigned long long r;
    asm("add.rn.f32x2 %0, %1, %2;" : "=l"(r) : "l"(a), "l"(b));
    return r;
}
// HW tanh (sm_75+): 1 MUFU op; sigmoid via tanh.
__device__ __forceinline__ float th_(float x) {
    float r;
    asm("tanh.approx.f32 %0, %1;" : "=f"(r) : "f"(x));
    return r;
}
__device__ __forceinline__ float sig_(float x) {
    return fmaf(0.5f, th_(0.5f * x), 0.5f);
}

// ---------------- mma helpers (verified R8/R13/R15) ----------------
__device__ __forceinline__ unsigned smem_u32(const void* p) {
    return (unsigned)__cvta_generic_to_shared(p);
}
__device__ __forceinline__ void ldmx4(unsigned& a0, unsigned& a1, unsigned& a2,
                                      unsigned& a3, unsigned addr) {
    asm volatile("ldmatrix.sync.aligned.m8n8.x4.shared.b16 {%0,%1,%2,%3}, [%4];"
                 : "=r"(a0), "=r"(a1), "=r"(a2), "=r"(a3) : "r"(addr));
}
__device__ __forceinline__ void mma16816(float* d, unsigned a0, unsigned a1,
                                         unsigned a2, unsigned a3,
                                         unsigned b0, unsigned b1) {
    asm volatile(
        "mma.sync.aligned.m16n8k16.row.col.f32.f16.f16.f32 "
        "{%0,%1,%2,%3}, {%4,%5,%6,%7}, {%8,%9}, {%0,%1,%2,%3};"
        : "+f"(d[0]), "+f"(d[1]), "+f"(d[2]), "+f"(d[3])
        : "r"(a0), "r"(a1), "r"(a2), "r"(a3), "r"(b0), "r"(b1));
}

// ---------------------------------------------------------------------------
// Input projection via tensor cores, coalesced stores (R13-proven WIN).
// ---------------------------------------------------------------------------
template <int D, int N>
__global__ void __launch_bounds__(256)
lstm_projM(const float* __restrict__ xin, const float* __restrict__ Wih,
           const float* __restrict__ bih, const float* __restrict__ bhh,
           __half* __restrict__ gx)
{
    constexpr int KT = D / 16;
    constexpr int NTILES = N / 64;
    constexpr int NCW = N / 8;
    constexpr int XPAD = D + 8;
    constexpr int OPAD = N + 8;

    __shared__ __align__(16) __half xs[32][XPAD];
    __shared__ __align__(16) __half os[32][OPAD];

    const int tid = threadIdx.x;
    const int w = tid >> 5, l = tid & 31;
    const int l4 = l & 3, lq = l >> 2;
    const int wbase = w * NCW;

    unsigned bf[KT][NTILES][2];
#pragma unroll
    for (int kt = 0; kt < KT; kt++)
#pragma unroll
        for (int ti = 0; ti < NTILES; ti++) {
            int n = wbase + ti * 8 + lq;
            int k0 = kt * 16 + 2 * l4;
            __half2 v0 = __floats2half2_rn(__ldg(&Wih[n * D + k0]),
                                           __ldg(&Wih[n * D + k0 + 1]));
            __half2 v1 = __floats2half2_rn(__ldg(&Wih[n * D + k0 + 8]),
                                           __ldg(&Wih[n * D + k0 + 9]));
            bf[kt][ti][0] = *(unsigned*)&v0;
            bf[kt][ti][1] = *(unsigned*)&v1;
        }
    float2 b2[NTILES];
#pragma unroll
    for (int ti = 0; ti < NTILES; ti++) {
        int n0 = wbase + ti * 8 + 2 * l4;
        b2[ti] = make_float2(__ldg(&bih[n0]) + __ldg(&bhh[n0]),
                             __ldg(&bih[n0 + 1]) + __ldg(&bhh[n0 + 1]));
    }

    const int arow = l & 15, acg = (l >> 4) * 8;
    const int ntiles_tot = (BB * TT) / 32;

#pragma unroll 1
    for (int tile = blockIdx.x; tile < ntiles_tot; tile += gridDim.x) {
        __syncthreads();
#pragma unroll 1
        for (int i = tid; i < 32 * (D / 4); i += 256) {
            int row = i / (D / 4), k4 = i % (D / 4);
            float4 v = ((const float4*)(xin + (size_t)(tile * 32 + row) * D))[k4];
            *(__half2*)&xs[row][4 * k4]     = __floats2half2_rn(v.x, v.y);
            *(__half2*)&xs[row][4 * k4 + 2] = __floats2half2_rn(v.z, v.w);
        }
        __syncthreads();

#pragma unroll
        for (int mt = 0; mt < 2; mt++) {
            unsigned aa[KT][4];
#pragma unroll
            for (int kt = 0; kt < KT; kt++)
                ldmx4(aa[kt][0], aa[kt][1], aa[kt][2], aa[kt][3],
                      smem_u32(&xs[mt * 16 + arow][acg + 16 * kt]));

            float d[NTILES][4];
#pragma unroll
            for (int ti = 0; ti < NTILES; ti++) {
                d[ti][0] = b2[ti].x; d[ti][1] = b2[ti].y;
                d[ti][2] = b2[ti].x; d[ti][3] = b2[ti].y;
            }
#pragma unroll
            for (int kt = 0; kt < KT; kt++)
#pragma unroll
                for (int ti = 0; ti < NTILES; ti++)
                    mma16816(d[ti], aa[kt][0], aa[kt][1], aa[kt][2], aa[kt][3],
                             bf[kt][ti][0], bf[kt][ti][1]);

#pragma unroll
            for (int ti = 0; ti < NTILES; ti++)
#pragma unroll
                for (int rr = 0; rr < 2; rr++)
                    *(__half2*)&os[mt * 16 + lq + 8 * rr][wbase + ti * 8 + 2 * l4] =
                        __floats2half2_rn(d[ti][2 * rr], d[ti][2 * rr + 1]);
        }
        __syncthreads();

#pragma unroll 1
        for (int i = tid; i < 32 * (N / 8); i += 256) {
            int row = i / (N / 8), c8 = i % (N / 8);
            int m = tile * 32 + row;
            int b = m >> 9, t = m & 511;
            *(float4*)(gx + ((size_t)t * BB + b) * N + 8 * c8) =
                *(const float4*)&os[row][8 * c8];
        }
    }
}

// ---------------------------------------------------------------------------
// Small-layer recurrence (R14/R15-proven FFMA2), Bc=4, fp16 gx, depth-2
// prefetch. 128 blocks.
// ---------------------------------------------------------------------------
template <int H>
__global__ void __launch_bounds__(4 * H)
lstm_recur_small(const __half* __restrict__ gx,  // [T][B][4H] fp16
                 const float* __restrict__ Whh,  // [4H][H]
                 float* __restrict__ out)        // [B][T][H]
{
    constexpr int G = 4 * H;
    const int col = threadIdx.x;
    const int b0 = blockIdx.x * 4;

    unsigned long long wh2[H];
#pragma unroll
    for (int k = 0; k < H; k++) {
        float w = __ldg(&Whh[col * H + k]);
        wh2[k] = pk2(w, w);
    }

    __shared__ __align__(16) unsigned long long h2[H][2];
    __shared__ __align__(16) unsigned long long g2[G][2];
    ((float*)h2)[col] = 0.f;

    const int hcol = col >> 2, er = col & 3;
    const int erp = er >> 1, elane = er & 1;
    float c = 0.f;

    const __half* gbase = gx + (size_t)b0 * G + col;
    const size_t ts = (size_t)BB * G;

    __half A0 = gbase[0], A1 = gbase[G], A2 = gbase[2 * G], A3 = gbase[3 * G];
    __half B0 = gbase[ts], B1 = gbase[ts + G], B2 = gbase[ts + 2 * G], B3 = gbase[ts + 3 * G];
    __syncthreads();

    const ulonglong2* hp2 = (const ulonglong2*)h2;

    for (int t = 0; t < TT; t++) {
        __half C0 = __float2half(0.f), C1 = C0, C2 = C0, C3 = C0;
        if (t + 2 < TT) {
            const __half* gp = gbase + (size_t)(t + 2) * ts;
            C0 = gp[0]; C1 = gp[G]; C2 = gp[2 * G]; C3 = gp[3 * G];
        }
        unsigned long long a00 = 0, a01 = 0, a10 = 0, a11 = 0;
#pragma unroll
        for (int k = 0; k < H; k += 2) {
            ulonglong2 ha = hp2[k];
            ulonglong2 hb = hp2[k + 1];
            fma2_(a00, wh2[k], ha.x);     fma2_(a01, wh2[k], ha.y);
            fma2_(a10, wh2[k + 1], hb.x); fma2_(a11, wh2[k + 1], hb.y);
        }
        ulonglong2 s;
        s.x = add2_(add2_(a00, a10), pk2(__half2float(A0), __half2float(A1)));
        s.y = add2_(add2_(a01, a11), pk2(__half2float(A2), __half2float(A3)));
        ((ulonglong2*)g2)[col] = s;
        A0 = B0; A1 = B1; A2 = B2; A3 = B3;
        B0 = C0; B1 = C1; B2 = C2; B3 = C3;
        __syncthreads();

        {
            const float* gf = (const float*)g2;
            int base = 4 * hcol + 2 * erp + elane;
            float gi = gf[base];
            float gF = gf[base + 4 * H];
            float gg = gf[base + 8 * H];
            float go = gf[base + 12 * H];
            c = sig_(gF) * c + sig_(gi) * th_(gg);
            float h = sig_(go) * th_(c);
            ((float*)h2)[base] = h;
            out[((size_t)(b0 + er) * TT + t) * H + hcol] = h;
        }
        __syncthreads();
    }
}

// ---------------------------------------------------------------------------
// Layer-3 recurrence: 2-CTA cluster (was 4), 256 threads (8 warps).
// CTA rank r owns h-cols [64r, 64r+64); warp w owns [64r+8w, 64r+8w+8).
// Same per-warp mma work as R15, but barrier spans 2 CTAs and DSMEM
// broadcast goes to 1 peer (less skew, less remote traffic).
// ---------------------------------------------------------------------------
#define CLUSTER 2
#define HPAD3 136   // half stride per h row (272B -> conflict-free ldmatrix)

__global__ void __launch_bounds__(256, 1) __cluster_dims__(CLUSTER, 1, 1)
lstm_recur_cluster(const __half* __restrict__ gx,   // [T][B][512] fp16
                   const float* __restrict__ Whh,   // [512][128] Whh3
                   float* __restrict__ out,         // [B][T][128]
                   float* __restrict__ hn)          // [B][128]
{
    __shared__ __align__(16) __half hsm[2][16][HPAD3];

    const int tid = threadIdx.x;
    const int w = tid >> 5, l = tid & 31;
    const int l4 = l & 3, lq = l >> 2;
    unsigned rank;
    asm("mov.u32 %0, %%cluster_ctarank;" : "=r"(rank));
    const int b0 = (blockIdx.x >> 1) * 16;
    const int hbase = 64 * (int)rank + 8 * w;    // warp h-col base

    unsigned bf[8][4][2];
#pragma unroll
    for (int kt = 0; kt < 8; kt++)
#pragma unroll
        for (int g = 0; g < 4; g++) {
            int n = 128 * g + hbase + lq;
            int k0 = 16 * kt + 2 * l4;
            __half2 v0 = __floats2half2_rn(__ldg(&Whh[n * 128 + k0]),
                                           __ldg(&Whh[n * 128 + k0 + 1]));
            __half2 v1 = __floats2half2_rn(__ldg(&Whh[n * 128 + k0 + 8]),
                                           __ldg(&Whh[n * 128 + k0 + 9]));
            bf[kt][g][0] = *(unsigned*)&v0;
            bf[kt][g][1] = *(unsigned*)&v1;
        }

    for (int i = tid; i < 16 * HPAD3 / 2; i += 256)
        ((unsigned*)&hsm[1][0][0])[i] = 0u;

    unsigned mybase = smem_u32(&hsm[0][0][0]);
    unsigned peer[CLUSTER];
#pragma unroll
    for (int r = 0; r < CLUSTER; r++)
        asm("mapa.shared::cluster.u32 %0, %1, %2;" : "=r"(peer[r]) : "r"(mybase), "r"(r));

    __syncthreads();
    asm volatile("barrier.cluster.arrive.aligned;" ::: "memory");
    asm volatile("barrier.cluster.wait.aligned;" ::: "memory");

    float c[4];
#pragma unroll
    for (int i = 0; i < 4; i++) c[i] = 0.f;

    const int arow = l & 15, acg = (l >> 4) * 8;

    unsigned gxf[8];
    {
        const __half* gp = gx + (size_t)(b0 + lq) * 512 + hbase + 2 * l4;
#pragma unroll
        for (int g = 0; g < 4; g++)
#pragma unroll
            for (int rr = 0; rr < 2; rr++)
                gxf[g * 2 + rr] = *(const unsigned*)(gp + g * 128 + rr * 8 * 512);
    }

    for (int t = 0; t < TT; t++) {
        const int rb = (t + 1) & 1;
        const int wb = t & 1;

        unsigned gxn[8];
        if (t + 1 < TT) {
            const __half* gp = gx + ((size_t)(t + 1) * BB + (b0 + lq)) * 512 + hbase + 2 * l4;
#pragma unroll
            for (int g = 0; g < 4; g++)
#pragma unroll
                for (int rr = 0; rr < 2; rr++)
                    gxn[g * 2 + rr] = *(const unsigned*)(gp + g * 128 + rr * 8 * 512);
        }

        float d[4][4];
#pragma unroll
        for (int g = 0; g < 4; g++)
#pragma unroll
            for (int rr = 0; rr < 2; rr++) {
                float2 f = __half22float2(*(__half2*)&gxf[g * 2 + rr]);
                d[g][2 * rr + 0] = f.x;
                d[g][2 * rr + 1] = f.y;
            }

#pragma unroll
        for (int kt = 0; kt < 8; kt++) {
            unsigned a0, a1, a2, a3;
            ldmx4(a0, a1, a2, a3, smem_u32(&hsm[rb][arow][acg + 16 * kt]));
#pragma unroll
            for (int g = 0; g < 4; g++)
                mma16816(d[g], a0, a1, a2, a3, bf[kt][g][0], bf[kt][g][1]);
        }

        float h[4];
#pragma unroll
        for (int reg = 0; reg < 4; reg++) {
            float gi = d[0][reg], gF = d[1][reg], gg = d[2][reg], go = d[3][reg];
            c[reg] = sig_(gF) * c[reg] + sig_(gi) * th_(gg);
            h[reg] = sig_(go) * th_(c[reg]);
        }
        __half2 hA = __floats2half2_rn(h[0], h[1]);
        __half2 hB = __floats2half2_rn(h[2], h[3]);
        unsigned offA = ((wb * 16 + lq) * HPAD3 + hbase + 2 * l4) * 2;
        unsigned offB = ((wb * 16 + lq + 8) * HPAD3 + hbase + 2 * l4) * 2;
        unsigned hA32 = *(unsigned*)&hA, hB32 = *(unsigned*)&hB;
#pragma unroll
        for (int r = 0; r < CLUSTER; r++) {
            asm volatile("st.shared::cluster.u32 [%0], %1;" :: "r"(peer[r] + offA), "r"(hA32) : "memory");
            asm volatile("st.shared::cluster.u32 [%0], %1;" :: "r"(peer[r] + offB), "r"(hB32) : "memory");
        }
        asm volatile("barrier.cluster.arrive.aligned;" ::: "memory");

        {
            int hc = hbase + 2 * l4;
            *(float2*)(out + ((size_t)(b0 + lq) * TT + t) * 128 + hc) = make_float2(h[0], h[1]);
            *(float2*)(out + ((size_t)(b0 + lq + 8) * TT + t) * 128 + hc) = make_float2(h[2], h[3]);
            if (t == TT - 1) {
                *(float2*)(hn + (size_t)(b0 + lq) * 128 + hc) = make_float2(h[0], h[1]);
                *(float2*)(hn + (size_t)(b0 + lq + 8) * 128 + hc) = make_float2(h[2], h[3]);
            }
        }
#pragma unroll
        for (int i = 0; i < 8; i++) gxf[i] = gxn[i];

        asm volatile("barrier.cluster.wait.aligned;" ::: "memory");
    }
}

// ---------------------------------------------------------------------------
extern "C" void kernel_launch(void* const* d_in, const int* in_sizes, int n_in,
                              void* d_out, int out_size)
{
    const float* z    = (const float*)d_in[0];
    const float* Wih1 = (const float*)d_in[1];
    const float* Whh1 = (const float*)d_in[2];
    const float* bih1 = (const float*)d_in[3];
    const float* bhh1 = (const float*)d_in[4];
    const float* Wih2 = (const float*)d_in[5];
    const float* Whh2 = (const float*)d_in[6];
    const float* bih2 = (const float*)d_in[7];
    const float* bhh2 = (const float*)d_in[8];
    const float* Wih3 = (const float*)d_in[9];
    const float* Whh3 = (const float*)d_in[10];
    const float* bih3 = (const float*)d_in[11];
    const float* bhh3 = (const float*)d_in[12];

    float* dec = (float*)d_out;                        // [B,T,128]
    float* hn  = dec + (size_t)BB * TT * 128;          // [1,B,128]

    __half* gx;
    float *h1, *h2;
    cudaGetSymbolAddress((void**)&gx, g_gxh);
    cudaGetSymbolAddress((void**)&h1, g_h1);
    cudaGetSymbolAddress((void**)&h2, g_h2);

    // Layer 1: 64 -> 32
    lstm_projM<64, 128><<<2048, 256>>>(z, Wih1, bih1, bhh1, gx);
    lstm_recur_small<32><<<BB / 4, 128>>>(gx, Whh1, h1);

    // Layer 2: 32 -> 48
    lstm_projM<32, 192><<<2048, 256>>>(h1, Wih2, bih2, bhh2, gx);
    lstm_recur_small<48><<<BB / 4, 192>>>(gx, Whh2, h2);

    // Layer 3: 48 -> 128
    lstm_projM<48, 512><<<2048, 256>>>(h2, Wih3, bih3, bhh3, gx);
    lstm_recur_cluster<<<BB / 16 * CLUSTER, 256>>>(gx, Whh3, dec, hn);
}